// round 5
// baseline (speedup 1.0000x reference)
#include <cuda_runtime.h>
#include <cstdint>

#define DIMC 1024
#define NH 16
#define HD 64
#define BB 4
#define TT 2048
#define BT (BB*TT)   // 8192

// Scratch (device globals: allocation-free contract)
__device__ float g_qkv[BT * 3 * DIMC];   // 96 MB
__device__ float g_q[BT * DIMC];         // [B,H,T,D]
__device__ float g_k[BT * DIMC];
__device__ float g_v[BT * DIMC];
__device__ float g_y[BT * DIMC];         // attention out, [B,T,H,D] = [BT, C]

// ---------------------------------------------------------------------------
// TF32 helpers
// ---------------------------------------------------------------------------
__device__ __forceinline__ uint32_t f2tf32(float f) {
    uint32_t u;
    asm("cvt.rna.tf32.f32 %0, %1;" : "=r"(u) : "f"(f));
    return u;
}

__device__ __forceinline__ void mma_tf32(float c[4],
    uint32_t a0, uint32_t a1, uint32_t a2, uint32_t a3,
    uint32_t b0, uint32_t b1)
{
    asm volatile(
        "mma.sync.aligned.m16n8k8.row.col.f32.tf32.tf32.f32 "
        "{%0,%1,%2,%3}, {%4,%5,%6,%7}, {%8,%9}, {%0,%1,%2,%3};"
        : "+f"(c[0]), "+f"(c[1]), "+f"(c[2]), "+f"(c[3])
        : "r"(a0), "r"(a1), "r"(a2), "r"(a3), "r"(b0), "r"(b1));
}

// ---------------------------------------------------------------------------
// TF32 GEMM: C[M,N] = A[M,K] @ B[K,N], row-major fp32 in/out.
// Block 128x128, BK=16, 256 threads (8 warps, 2m x 4n), warp tile 64x32.
// Double-buffered smem + register prefetch: one __syncthreads per K-step.
// ---------------------------------------------------------------------------
#define AST 20
#define BST 136
__global__ __launch_bounds__(256, 2) void gemm_tf32(
    const float* __restrict__ A, const float* __restrict__ Bm,
    float* __restrict__ C, int M, int N, int K)
{
    __shared__ uint32_t As[2][128 * AST];   // [m][k]
    __shared__ uint32_t Bs[2][16 * BST];    // [k][n]

    const int tid  = threadIdx.x;
    const int lane = tid & 31;
    const int warp = tid >> 5;
    const int wm = warp & 1;
    const int wn = warp >> 1;
    const int m0 = blockIdx.y << 7;
    const int n0 = blockIdx.x << 7;
    const int m0w = wm * 64;
    const int n0w = wn * 32;

    const int row = lane >> 2;
    const int tig = lane & 3;

    // load indices (2 float4 per thread per tile for each of A, B)
    const int raA0 = (tid + 0)   >> 2, caA0 = ((tid + 0)   & 3) << 2;
    const int raA1 = (tid + 256) >> 2, caA1 = ((tid + 256) & 3) << 2;
    const int rbB0 = (tid + 0)   >> 5, cbB0 = ((tid + 0)   & 31) << 2;
    const int rbB1 = (tid + 256) >> 5, cbB1 = ((tid + 256) & 31) << 2;

    float acc[4][4][4];
    #pragma unroll
    for (int i = 0; i < 4; i++)
        #pragma unroll
        for (int j = 0; j < 4; j++)
            #pragma unroll
            for (int r = 0; r < 4; r++) acc[i][j][r] = 0.0f;

    const int KT = K >> 4;

    // prologue: load tile 0 and store to buffer 0
    float4 a0 = *(const float4*)&A[(size_t)(m0 + raA0) * K + caA0];
    float4 a1 = *(const float4*)&A[(size_t)(m0 + raA1) * K + caA1];
    float4 b0 = *(const float4*)&Bm[(size_t)rbB0 * N + n0 + cbB0];
    float4 b1 = *(const float4*)&Bm[(size_t)rbB1 * N + n0 + cbB1];
    {
        uint4 u;
        u.x = f2tf32(a0.x); u.y = f2tf32(a0.y); u.z = f2tf32(a0.z); u.w = f2tf32(a0.w);
        *(uint4*)&As[0][raA0 * AST + caA0] = u;
        u.x = f2tf32(a1.x); u.y = f2tf32(a1.y); u.z = f2tf32(a1.z); u.w = f2tf32(a1.w);
        *(uint4*)&As[0][raA1 * AST + caA1] = u;
        u.x = f2tf32(b0.x); u.y = f2tf32(b0.y); u.z = f2tf32(b0.z); u.w = f2tf32(b0.w);
        *(uint4*)&Bs[0][rbB0 * BST + cbB0] = u;
        u.x = f2tf32(b1.x); u.y = f2tf32(b1.y); u.z = f2tf32(b1.z); u.w = f2tf32(b1.w);
        *(uint4*)&Bs[0][rbB1 * BST + cbB1] = u;
    }
    __syncthreads();

    for (int ki = 0; ki < KT; ki++) {
        const int cur = ki & 1;
        const int nxt = cur ^ 1;
        const bool more = (ki + 1) < KT;

        // prefetch next tile into registers (latency overlaps the MMAs below)
        if (more) {
            int k0 = (ki + 1) << 4;
            a0 = *(const float4*)&A[(size_t)(m0 + raA0) * K + k0 + caA0];
            a1 = *(const float4*)&A[(size_t)(m0 + raA1) * K + k0 + caA1];
            b0 = *(const float4*)&Bm[(size_t)(k0 + rbB0) * N + n0 + cbB0];
            b1 = *(const float4*)&Bm[(size_t)(k0 + rbB1) * N + n0 + cbB1];
        }

        const uint32_t* Ac = &As[cur][0];
        const uint32_t* Bc = &Bs[cur][0];
        #pragma unroll
        for (int kc = 0; kc < 16; kc += 8) {
            uint32_t af[4][4], bf[4][2];
            #pragma unroll
            for (int mt = 0; mt < 4; mt++) {
                int mr = m0w + mt * 16 + row;
                af[mt][0] = Ac[mr * AST + kc + tig];
                af[mt][1] = Ac[(mr + 8) * AST + kc + tig];
                af[mt][2] = Ac[mr * AST + kc + tig + 4];
                af[mt][3] = Ac[(mr + 8) * AST + kc + tig + 4];
            }
            #pragma unroll
            for (int nt = 0; nt < 4; nt++) {
                int nc = n0w + nt * 8 + row;
                bf[nt][0] = Bc[(kc + tig) * BST + nc];
                bf[nt][1] = Bc[(kc + tig + 4) * BST + nc];
            }
            #pragma unroll
            for (int mt = 0; mt < 4; mt++)
                #pragma unroll
                for (int nt = 0; nt < 4; nt++)
                    mma_tf32(acc[mt][nt], af[mt][0], af[mt][1], af[mt][2], af[mt][3],
                             bf[nt][0], bf[nt][1]);
        }

        // store prefetched tile into the other buffer
        if (more) {
            uint4 u;
            u.x = f2tf32(a0.x); u.y = f2tf32(a0.y); u.z = f2tf32(a0.z); u.w = f2tf32(a0.w);
            *(uint4*)&As[nxt][raA0 * AST + caA0] = u;
            u.x = f2tf32(a1.x); u.y = f2tf32(a1.y); u.z = f2tf32(a1.z); u.w = f2tf32(a1.w);
            *(uint4*)&As[nxt][raA1 * AST + caA1] = u;
            u.x = f2tf32(b0.x); u.y = f2tf32(b0.y); u.z = f2tf32(b0.z); u.w = f2tf32(b0.w);
            *(uint4*)&Bs[nxt][rbB0 * BST + cbB0] = u;
            u.x = f2tf32(b1.x); u.y = f2tf32(b1.y); u.z = f2tf32(b1.z); u.w = f2tf32(b1.w);
            *(uint4*)&Bs[nxt][rbB1 * BST + cbB1] = u;
        }
        __syncthreads();
    }

    #pragma unroll
    for (int mt = 0; mt < 4; mt++) {
        int mr = m0 + m0w + mt * 16 + row;
        #pragma unroll
        for (int nt = 0; nt < 4; nt++) {
            int nc = n0 + n0w + nt * 8 + 2 * tig;
            float2 lo = { acc[mt][nt][0], acc[mt][nt][1] };
            float2 hi = { acc[mt][nt][2], acc[mt][nt][3] };
            *(float2*)&C[(size_t)mr * N + nc] = lo;
            *(float2*)&C[(size_t)(mr + 8) * N + nc] = hi;
        }
    }
}

// ---------------------------------------------------------------------------
// RoPE + split + reshape (unchanged)
// ---------------------------------------------------------------------------
__global__ __launch_bounds__(256) void rope_split(
    const float* __restrict__ qkv,
    float* __restrict__ Q, float* __restrict__ K, float* __restrict__ V)
{
    int gid = blockIdx.x * 256 + threadIdx.x;
    if (gid >= BT * DIMC) return;

    int d  = gid & 63;
    int h  = (gid >> 6) & 15;
    int bt = gid >> 10;
    int t  = bt & (TT - 1);
    int b  = bt >> 11;

    const float* row = qkv + (size_t)bt * (3 * DIMC);

    int j = d & 31;
    float freq = __expf(-(float)j * 0.28782313662425575f);
    float ang = (float)t * freq;
    float s, c;
    sincosf(ang, &s, &c);

    int pair = (d < 32) ? d + 32 : d - 32;
    float sign = (d < 32) ? -1.0f : 1.0f;

    float qv = row[h * 64 + d];
    float qp = row[h * 64 + pair];
    float kv = row[DIMC + h * 64 + d];
    float kp = row[DIMC + h * 64 + pair];
    float vv = row[2 * DIMC + h * 64 + d];

    size_t o = ((size_t)(b * NH + h) * TT + t) * HD + d;
    Q[o] = (qv * c + sign * qp * s) * 0.125f;
    K[o] =  kv * c + sign * kp * s;
    V[o] =  vv;
}

// ---------------------------------------------------------------------------
// Tensor-core flash attention (causal). Q-tile 128 x K-tile 64, 256 threads
// (8 warps); each warp owns 16 full query rows -> softmax is warp-local.
// Q fragments (tf32 hi + residual) in registers. K/V/P smem conflict-free.
// ---------------------------------------------------------------------------
#define KST 68
#define VST 72
#define PST 72
__global__ __launch_bounds__(256, 2) void attn_tc(
    const float* __restrict__ Q, const float* __restrict__ K,
    const float* __restrict__ V, float* __restrict__ Y)
{
    extern __shared__ uint32_t smw[];
    uint32_t* Ks = smw;                // [kseq][d]   64 x KST
    uint32_t* Vs = Ks + 64 * KST;      // [kseq][d]   64 x VST
    uint32_t* Ps = Vs + 64 * VST;      // [q][kseq]  128 x PST

    const int tid  = threadIdx.x;
    const int lane = tid & 31;
    const int warp = tid >> 5;         // 0..7
    const int row  = lane >> 2;        // 0..7
    const int tig  = lane & 3;         // 0..3
    const int qb = blockIdx.x;         // 0..15 (128-row q tiles)
    const int bh = blockIdx.y;
    const int b  = bh >> 4;
    const int h  = bh & 15;
    const int r0 = warp * 16 + row;    // owned rows r0, r0+8 (0..127)
    const int q0 = qb * 128;

    const float* Qg = Q + ((size_t)bh * TT + q0) * HD;
    const float* Kg = K + (size_t)bh * TT * HD;
    const float* Vg = V + (size_t)bh * TT * HD;

    // Q fragments in registers: hi + residual, 8 k-steps x 4 regs each
    uint32_t qh[8][4], qr[8][4];
    #pragma unroll
    for (int s = 0; s < 8; s++) {
        float f0 = Qg[r0 * 64 + 8 * s + tig];
        float f1 = Qg[(r0 + 8) * 64 + 8 * s + tig];
        float f2 = Qg[r0 * 64 + 8 * s + tig + 4];
        float f3 = Qg[(r0 + 8) * 64 + 8 * s + tig + 4];
        qh[s][0] = f2tf32(f0); qr[s][0] = f2tf32(f0 - __uint_as_float(qh[s][0]));
        qh[s][1] = f2tf32(f1); qr[s][1] = f2tf32(f1 - __uint_as_float(qh[s][1]));
        qh[s][2] = f2tf32(f2); qr[s][2] = f2tf32(f2 - __uint_as_float(qh[s][2]));
        qh[s][3] = f2tf32(f3); qr[s][3] = f2tf32(f3 - __uint_as_float(qh[s][3]));
    }

    float m_[2] = { -1e30f, -1e30f };
    float l_[2] = { 0.0f, 0.0f };
    float oacc[8][4];
    #pragma unroll
    for (int nt = 0; nt < 8; nt++)
        #pragma unroll
        for (int r = 0; r < 4; r++) oacc[nt][r] = 0.0f;

    const int nkb = 2 * qb + 2;
    for (int kb = 0; kb < nkb; kb++) {
        __syncthreads();   // all warps done reading Ks/Vs from previous iter
        #pragma unroll
        for (int it = 0; it < 4; it++) {
            int idx = tid + it * 256;
            int k  = idx >> 4;
            int d0 = (idx & 15) << 2;
            float4 kv = *(const float4*)&Kg[(size_t)(kb * 64 + k) * 64 + d0];
            float4 vv = *(const float4*)&Vg[(size_t)(kb * 64 + k) * 64 + d0];
            uint4 ku = { f2tf32(kv.x), f2tf32(kv.y), f2tf32(kv.z), f2tf32(kv.w) };
            uint4 vu = { f2tf32(vv.x), f2tf32(vv.y), f2tf32(vv.z), f2tf32(vv.w) };
            *(uint4*)&Ks[k * KST + d0] = ku;
            *(uint4*)&Vs[k * VST + d0] = vu;
        }
        __syncthreads();

        // warps whose rows are entirely above this k block skip compute
        const bool active = !(kb == 2 * qb + 1 && warp < 4);
        if (active) {
            // S = Q @ K^T (split-Q: 2 MMAs per tile)
            float sacc[8][4];
            #pragma unroll
            for (int nt = 0; nt < 8; nt++)
                #pragma unroll
                for (int r = 0; r < 4; r++) sacc[nt][r] = 0.0f;

            #pragma unroll
            for (int s = 0; s < 8; s++) {
                int kc = 8 * s;
                #pragma unroll
                for (int nt = 0; nt < 8; nt++) {
                    int nc = nt * 8 + row;
                    uint32_t kb0 = Ks[nc * KST + kc + tig];
                    uint32_t kb1 = Ks[nc * KST + kc + tig + 4];
                    mma_tf32(sacc[nt], qh[s][0], qh[s][1], qh[s][2], qh[s][3], kb0, kb1);
                    mma_tf32(sacc[nt], qr[s][0], qr[s][1], qr[s][2], qr[s][3], kb0, kb1);
                }
            }

            if (kb >= 2 * qb) {   // only the last two k blocks can cross the diagonal
                #pragma unroll
                for (int nt = 0; nt < 8; nt++)
                    #pragma unroll
                    for (int r = 0; r < 4; r++) {
                        int ql = q0 + r0 + 8 * (r >> 1);
                        int kl = kb * 64 + nt * 8 + 2 * tig + (r & 1);
                        if (kl > ql) sacc[nt][r] = -1e30f;
                    }
            }

            // warp-local online softmax
            #pragma unroll
            for (int hh = 0; hh < 2; hh++) {
                float mx = -1e30f;
                #pragma unroll
                for (int nt = 0; nt < 8; nt++)
                    mx = fmaxf(mx, fmaxf(sacc[nt][2 * hh], sacc[nt][2 * hh + 1]));
                mx = fmaxf(mx, __shfl_xor_sync(0xffffffffu, mx, 1));
                mx = fmaxf(mx, __shfl_xor_sync(0xffffffffu, mx, 2));
                float mnew = fmaxf(m_[hh], mx);
                float alpha = __expf(m_[hh] - mnew);
                m_[hh] = mnew;
                float rs = 0.0f;
                int qrow = r0 + 8 * hh;
                #pragma unroll
                for (int nt = 0; nt < 8; nt++) {
                    float p0 = __expf(sacc[nt][2 * hh] - mnew);
                    float p1 = __expf(sacc[nt][2 * hh + 1] - mnew);
                    rs += p0 + p1;
                    uint2 pu = { f2tf32(p0), f2tf32(p1) };
                    *(uint2*)&Ps[qrow * PST + nt * 8 + 2 * tig] = pu;
                    oacc[nt][2 * hh]     *= alpha;
                    oacc[nt][2 * hh + 1] *= alpha;
                }
                rs += __shfl_xor_sync(0xffffffffu, rs, 1);
                rs += __shfl_xor_sync(0xffffffffu, rs, 2);
                l_[hh] = l_[hh] * alpha + rs;
            }
            __syncwarp();   // Ps rows are warp-private

            // O += P @ V
            #pragma unroll
            for (int s = 0; s < 8; s++) {
                int kc = 8 * s;
                uint32_t a0 = Ps[r0 * PST + kc + tig];
                uint32_t a1 = Ps[(r0 + 8) * PST + kc + tig];
                uint32_t a2 = Ps[r0 * PST + kc + tig + 4];
                uint32_t a3 = Ps[(r0 + 8) * PST + kc + tig + 4];
                #pragma unroll
                for (int nt = 0; nt < 8; nt++) {
                    int nc = nt * 8 + row;
                    uint32_t vb0 = Vs[(kc + tig) * VST + nc];
                    uint32_t vb1 = Vs[(kc + tig + 4) * VST + nc];
                    mma_tf32(oacc[nt], a0, a1, a2, a3, vb0, vb1);
                }
            }
        }
    }

    // epilogue: normalize, write Y[B,T,H,D]
    #pragma unroll
    for (int hh = 0; hh < 2; hh++) {
        float inv = 1.0f / l_[hh];
        int qg = q0 + r0 + 8 * hh;
        size_t base = ((size_t)(b * TT + qg) * NH + h) * HD;
        #pragma unroll
        for (int nt = 0; nt < 8; nt++) {
            int d = nt * 8 + 2 * tig;
            float2 o2 = { oacc[nt][2 * hh] * inv, oacc[nt][2 * hh + 1] * inv };
            *(float2*)&Y[base + d] = o2;
        }
    }
}

// ---------------------------------------------------------------------------
extern "C" void kernel_launch(void* const* d_in, const int* in_sizes, int n_in,
                              void* d_out, int out_size)
{
    const float* x     = (const float*)d_in[0];   // [B,T,C]
    const float* Wqkv  = (const float*)d_in[1];   // [C, 3C]
    const float* Wproj = (const float*)d_in[2];   // [C, C]
    float* out = (float*)d_out;                   // [B,T,C]

    float *qkv, *q, *k, *v, *y;
    cudaGetSymbolAddress((void**)&qkv, g_qkv);
    cudaGetSymbolAddress((void**)&q,   g_q);
    cudaGetSymbolAddress((void**)&k,   g_k);
    cudaGetSymbolAddress((void**)&v,   g_v);
    cudaGetSymbolAddress((void**)&y,   g_y);

    // 1) qkv = x @ Wqkv   (8192 x 3072 x 1024)
    gemm_tf32<<<dim3(3 * DIMC / 128, BT / 128), 256>>>(x, Wqkv, qkv, BT, 3 * DIMC, DIMC);

    // 2) split + RoPE (+ q scaling)
    rope_split<<<(BT * DIMC + 255) / 256, 256>>>(qkv, q, k, v);

    // 3) causal flash attention (tensor cores, 128-row q tiles)
    const int smem_bytes = (64 * KST + 64 * VST + 128 * PST) * (int)sizeof(uint32_t); // 72704
    cudaFuncSetAttribute(attn_tc, cudaFuncAttributeMaxDynamicSharedMemorySize, smem_bytes);
    attn_tc<<<dim3(TT / 128, BB * NH), 256, smem_bytes>>>(q, k, v, y);

    // 4) out = y @ Wproj  (8192 x 1024 x 1024)
    gemm_tf32<<<dim3(DIMC / 128, BT / 128), 256>>>(y, Wproj, out, BT, DIMC, DIMC);
}

// round 7
// speedup vs baseline: 1.1665x; 1.1665x over previous
#include <cuda_runtime.h>
#include <cstdint>

#define DIMC 1024
#define NH 16
#define HD 64
#define BB 4
#define TT 2048
#define BT (BB*TT)   // 8192

// Scratch (device globals: allocation-free contract)
__device__ float g_qkv[BT * 3 * DIMC];   // 96 MB
__device__ float g_q[BT * DIMC];         // [B,H,T,D]
__device__ float g_k[BT * DIMC];
__device__ float g_v[BT * DIMC];
__device__ float g_y[BT * DIMC];         // attention out, [B,T,H,D] = [BT, C]

// ---------------------------------------------------------------------------
// TF32 helpers
// ---------------------------------------------------------------------------
__device__ __forceinline__ uint32_t f2tf32(float f) {
    uint32_t u;
    asm("cvt.rna.tf32.f32 %0, %1;" : "=r"(u) : "f"(f));
    return u;
}

__device__ __forceinline__ void mma_tf32(float c[4],
    uint32_t a0, uint32_t a1, uint32_t a2, uint32_t a3,
    uint32_t b0, uint32_t b1)
{
    asm volatile(
        "mma.sync.aligned.m16n8k8.row.col.f32.tf32.tf32.f32 "
        "{%0,%1,%2,%3}, {%4,%5,%6,%7}, {%8,%9}, {%0,%1,%2,%3};"
        : "+f"(c[0]), "+f"(c[1]), "+f"(c[2]), "+f"(c[3])
        : "r"(a0), "r"(a1), "r"(a2), "r"(a3), "r"(b0), "r"(b1));
}

// ---------------------------------------------------------------------------
// TF32 GEMM: C[M,N] = A[M,K] @ B[K,N], row-major fp32 in/out.
// Block 128x128, BK=16, 256 threads (8 warps, 2m x 4n), warp tile 64x32.
// Double-buffered smem + register prefetch: one __syncthreads per K-step.
// ---------------------------------------------------------------------------
#define AST 20
#define BST 136
__global__ __launch_bounds__(256, 2) void gemm_tf32(
    const float* __restrict__ A, const float* __restrict__ Bm,
    float* __restrict__ C, int M, int N, int K)
{
    __shared__ uint32_t As[2][128 * AST];   // [m][k]
    __shared__ uint32_t Bs[2][16 * BST];    // [k][n]

    const int tid  = threadIdx.x;
    const int lane = tid & 31;
    const int warp = tid >> 5;
    const int wm = warp & 1;
    const int wn = warp >> 1;
    const int m0 = blockIdx.y << 7;
    const int n0 = blockIdx.x << 7;
    const int m0w = wm * 64;
    const int n0w = wn * 32;

    const int row = lane >> 2;
    const int tig = lane & 3;

    const int raA0 = (tid + 0)   >> 2, caA0 = ((tid + 0)   & 3) << 2;
    const int raA1 = (tid + 256) >> 2, caA1 = ((tid + 256) & 3) << 2;
    const int rbB0 = (tid + 0)   >> 5, cbB0 = ((tid + 0)   & 31) << 2;
    const int rbB1 = (tid + 256) >> 5, cbB1 = ((tid + 256) & 31) << 2;

    float acc[4][4][4];
    #pragma unroll
    for (int i = 0; i < 4; i++)
        #pragma unroll
        for (int j = 0; j < 4; j++)
            #pragma unroll
            for (int r = 0; r < 4; r++) acc[i][j][r] = 0.0f;

    const int KT = K >> 4;

    float4 a0 = *(const float4*)&A[(size_t)(m0 + raA0) * K + caA0];
    float4 a1 = *(const float4*)&A[(size_t)(m0 + raA1) * K + caA1];
    float4 b0 = *(const float4*)&Bm[(size_t)rbB0 * N + n0 + cbB0];
    float4 b1 = *(const float4*)&Bm[(size_t)rbB1 * N + n0 + cbB1];
    {
        uint4 u;
        u.x = f2tf32(a0.x); u.y = f2tf32(a0.y); u.z = f2tf32(a0.z); u.w = f2tf32(a0.w);
        *(uint4*)&As[0][raA0 * AST + caA0] = u;
        u.x = f2tf32(a1.x); u.y = f2tf32(a1.y); u.z = f2tf32(a1.z); u.w = f2tf32(a1.w);
        *(uint4*)&As[0][raA1 * AST + caA1] = u;
        u.x = f2tf32(b0.x); u.y = f2tf32(b0.y); u.z = f2tf32(b0.z); u.w = f2tf32(b0.w);
        *(uint4*)&Bs[0][rbB0 * BST + cbB0] = u;
        u.x = f2tf32(b1.x); u.y = f2tf32(b1.y); u.z = f2tf32(b1.z); u.w = f2tf32(b1.w);
        *(uint4*)&Bs[0][rbB1 * BST + cbB1] = u;
    }
    __syncthreads();

    for (int ki = 0; ki < KT; ki++) {
        const int cur = ki & 1;
        const int nxt = cur ^ 1;
        const bool more = (ki + 1) < KT;

        if (more) {
            int k0 = (ki + 1) << 4;
            a0 = *(const float4*)&A[(size_t)(m0 + raA0) * K + k0 + caA0];
            a1 = *(const float4*)&A[(size_t)(m0 + raA1) * K + k0 + caA1];
            b0 = *(const float4*)&Bm[(size_t)(k0 + rbB0) * N + n0 + cbB0];
            b1 = *(const float4*)&Bm[(size_t)(k0 + rbB1) * N + n0 + cbB1];
        }

        const uint32_t* Ac = &As[cur][0];
        const uint32_t* Bc = &Bs[cur][0];
        #pragma unroll
        for (int kc = 0; kc < 16; kc += 8) {
            uint32_t af[4][4], bf[4][2];
            #pragma unroll
            for (int mt = 0; mt < 4; mt++) {
                int mr = m0w + mt * 16 + row;
                af[mt][0] = Ac[mr * AST + kc + tig];
                af[mt][1] = Ac[(mr + 8) * AST + kc + tig];
                af[mt][2] = Ac[mr * AST + kc + tig + 4];
                af[mt][3] = Ac[(mr + 8) * AST + kc + tig + 4];
            }
            #pragma unroll
            for (int nt = 0; nt < 4; nt++) {
                int nc = n0w + nt * 8 + row;
                bf[nt][0] = Bc[(kc + tig) * BST + nc];
                bf[nt][1] = Bc[(kc + tig + 4) * BST + nc];
            }
            #pragma unroll
            for (int mt = 0; mt < 4; mt++)
                #pragma unroll
                for (int nt = 0; nt < 4; nt++)
                    mma_tf32(acc[mt][nt], af[mt][0], af[mt][1], af[mt][2], af[mt][3],
                             bf[nt][0], bf[nt][1]);
        }

        if (more) {
            uint4 u;
            u.x = f2tf32(a0.x); u.y = f2tf32(a0.y); u.z = f2tf32(a0.z); u.w = f2tf32(a0.w);
            *(uint4*)&As[nxt][raA0 * AST + caA0] = u;
            u.x = f2tf32(a1.x); u.y = f2tf32(a1.y); u.z = f2tf32(a1.z); u.w = f2tf32(a1.w);
            *(uint4*)&As[nxt][raA1 * AST + caA1] = u;
            u.x = f2tf32(b0.x); u.y = f2tf32(b0.y); u.z = f2tf32(b0.z); u.w = f2tf32(b0.w);
            *(uint4*)&Bs[nxt][rbB0 * BST + cbB0] = u;
            u.x = f2tf32(b1.x); u.y = f2tf32(b1.y); u.z = f2tf32(b1.z); u.w = f2tf32(b1.w);
            *(uint4*)&Bs[nxt][rbB1 * BST + cbB1] = u;
        }
        __syncthreads();
    }

    #pragma unroll
    for (int mt = 0; mt < 4; mt++) {
        int mr = m0 + m0w + mt * 16 + row;
        #pragma unroll
        for (int nt = 0; nt < 4; nt++) {
            int nc = n0 + n0w + nt * 8 + 2 * tig;
            float2 lo = { acc[mt][nt][0], acc[mt][nt][1] };
            float2 hi = { acc[mt][nt][2], acc[mt][nt][3] };
            *(float2*)&C[(size_t)mr * N + nc] = lo;
            *(float2*)&C[(size_t)(mr + 8) * N + nc] = hi;
        }
    }
}

// ---------------------------------------------------------------------------
// RoPE + split + reshape (unchanged)
// ---------------------------------------------------------------------------
__global__ __launch_bounds__(256) void rope_split(
    const float* __restrict__ qkv,
    float* __restrict__ Q, float* __restrict__ K, float* __restrict__ V)
{
    int gid = blockIdx.x * 256 + threadIdx.x;
    if (gid >= BT * DIMC) return;

    int d  = gid & 63;
    int h  = (gid >> 6) & 15;
    int bt = gid >> 10;
    int t  = bt & (TT - 1);
    int b  = bt >> 11;

    const float* row = qkv + (size_t)bt * (3 * DIMC);

    int j = d & 31;
    float freq = __expf(-(float)j * 0.28782313662425575f);
    float ang = (float)t * freq;
    float s, c;
    sincosf(ang, &s, &c);

    int pair = (d < 32) ? d + 32 : d - 32;
    float sign = (d < 32) ? -1.0f : 1.0f;

    float qv = row[h * 64 + d];
    float qp = row[h * 64 + pair];
    float kv = row[DIMC + h * 64 + d];
    float kp = row[DIMC + h * 64 + pair];
    float vv = row[2 * DIMC + h * 64 + d];

    size_t o = ((size_t)(b * NH + h) * TT + t) * HD + d;
    Q[o] = (qv * c + sign * qp * s) * 0.125f;
    K[o] =  kv * c + sign * kp * s;
    V[o] =  vv;
}

// ---------------------------------------------------------------------------
// Tensor-core flash attention (causal). 64x64 tiles, 128 threads (4 warps).
// Each warp owns 16 full query rows (m16 x n64) -> softmax is warp-local.
// Single-TF32 QK (Q frags in registers), TF32 PV. Conflict-free smem strides.
// ---------------------------------------------------------------------------
#define KST 68
#define VST 72
#define PST 72
__global__ __launch_bounds__(128) void attn_tc(
    const float* __restrict__ Q, const float* __restrict__ K,
    const float* __restrict__ V, float* __restrict__ Y)
{
    extern __shared__ uint32_t smw[];
    uint32_t* Ks = smw;                // [kseq][d]  64 x KST
    uint32_t* Vs = Ks + 64 * KST;      // [kseq][d]  64 x VST
    uint32_t* Ps = Vs + 64 * VST;      // [q][kseq]  64 x PST

    const int tid  = threadIdx.x;
    const int lane = tid & 31;
    const int warp = tid >> 5;         // 0..3
    const int row  = lane >> 2;        // 0..7
    const int tig  = lane & 3;         // 0..3
    const int qb = blockIdx.x;
    const int bh = blockIdx.y;
    const int b  = bh >> 4;
    const int h  = bh & 15;
    const int r0 = warp * 16 + row;    // owned rows r0, r0+8

    const float* Qg = Q + ((size_t)bh * TT + qb * 64) * HD;
    const float* Kg = K + (size_t)bh * TT * HD;
    const float* Vg = V + (size_t)bh * TT * HD;

    // Q fragments in registers (single tf32), 8 k-steps x 4 regs
    uint32_t qh[8][4];
    #pragma unroll
    for (int s = 0; s < 8; s++) {
        qh[s][0] = f2tf32(Qg[r0 * 64 + 8 * s + tig]);
        qh[s][1] = f2tf32(Qg[(r0 + 8) * 64 + 8 * s + tig]);
        qh[s][2] = f2tf32(Qg[r0 * 64 + 8 * s + tig + 4]);
        qh[s][3] = f2tf32(Qg[(r0 + 8) * 64 + 8 * s + tig + 4]);
    }

    float m_[2] = { -1e30f, -1e30f };
    float l_[2] = { 0.0f, 0.0f };
    float oacc[8][4];
    #pragma unroll
    for (int nt = 0; nt < 8; nt++)
        #pragma unroll
        for (int r = 0; r < 4; r++) oacc[nt][r] = 0.0f;

    for (int kb = 0; kb <= qb; kb++) {
        __syncthreads();   // all warps done reading Ks/Vs from previous iter
        #pragma unroll
        for (int it = 0; it < 8; it++) {
            int idx = tid + it * 128;
            int k  = idx >> 4;
            int d0 = (idx & 15) << 2;
            float4 kv = *(const float4*)&Kg[(size_t)(kb * 64 + k) * 64 + d0];
            float4 vv = *(const float4*)&Vg[(size_t)(kb * 64 + k) * 64 + d0];
            uint4 ku = { f2tf32(kv.x), f2tf32(kv.y), f2tf32(kv.z), f2tf32(kv.w) };
            uint4 vu = { f2tf32(vv.x), f2tf32(vv.y), f2tf32(vv.z), f2tf32(vv.w) };
            *(uint4*)&Ks[k * KST + d0] = ku;
            *(uint4*)&Vs[k * VST + d0] = vu;
        }
        __syncthreads();

        // S = Q @ K^T
        float sacc[8][4];
        #pragma unroll
        for (int nt = 0; nt < 8; nt++)
            #pragma unroll
            for (int r = 0; r < 4; r++) sacc[nt][r] = 0.0f;

        #pragma unroll
        for (int s = 0; s < 8; s++) {
            int kc = 8 * s;
            #pragma unroll
            for (int nt = 0; nt < 8; nt++) {
                int nc = nt * 8 + row;
                uint32_t b0 = Ks[nc * KST + kc + tig];
                uint32_t b1 = Ks[nc * KST + kc + tig + 4];
                mma_tf32(sacc[nt], qh[s][0], qh[s][1], qh[s][2], qh[s][3], b0, b1);
            }
        }

        if (kb == qb) {   // causal mask on diagonal block
            #pragma unroll
            for (int nt = 0; nt < 8; nt++)
                #pragma unroll
                for (int r = 0; r < 4; r++) {
                    int ql = r0 + 8 * (r >> 1);
                    int kl = nt * 8 + 2 * tig + (r & 1);
                    if (kl > ql) sacc[nt][r] = -1e30f;
                }
        }

        // warp-local online softmax (full 64-col rows within this warp)
        #pragma unroll
        for (int hh = 0; hh < 2; hh++) {
            float mx = -1e30f;
            #pragma unroll
            for (int nt = 0; nt < 8; nt++)
                mx = fmaxf(mx, fmaxf(sacc[nt][2 * hh], sacc[nt][2 * hh + 1]));
            mx = fmaxf(mx, __shfl_xor_sync(0xffffffffu, mx, 1));
            mx = fmaxf(mx, __shfl_xor_sync(0xffffffffu, mx, 2));
            float mnew = fmaxf(m_[hh], mx);
            float alpha = __expf(m_[hh] - mnew);
            m_[hh] = mnew;
            float rs = 0.0f;
            int qrow = r0 + 8 * hh;
            #pragma unroll
            for (int nt = 0; nt < 8; nt++) {
                float p0 = __expf(sacc[nt][2 * hh] - mnew);
                float p1 = __expf(sacc[nt][2 * hh + 1] - mnew);
                rs += p0 + p1;
                uint2 pu = { f2tf32(p0), f2tf32(p1) };
                *(uint2*)&Ps[qrow * PST + nt * 8 + 2 * tig] = pu;
                oacc[nt][2 * hh]     *= alpha;
                oacc[nt][2 * hh + 1] *= alpha;
            }
            rs += __shfl_xor_sync(0xffffffffu, rs, 1);
            rs += __shfl_xor_sync(0xffffffffu, rs, 2);
            l_[hh] = l_[hh] * alpha + rs;
        }
        __syncwarp();   // Ps rows are warp-private; intra-warp visibility only

        // O += P @ V
        #pragma unroll
        for (int s = 0; s < 8; s++) {
            int kc = 8 * s;
            uint32_t a0 = Ps[r0 * PST + kc + tig];
            uint32_t a1 = Ps[(r0 + 8) * PST + kc + tig];
            uint32_t a2 = Ps[r0 * PST + kc + tig + 4];
            uint32_t a3 = Ps[(r0 + 8) * PST + kc + tig + 4];
            #pragma unroll
            for (int nt = 0; nt < 8; nt++) {
                int nc = nt * 8 + row;
                uint32_t b0 = Vs[(kc + tig) * VST + nc];
                uint32_t b1 = Vs[(kc + tig + 4) * VST + nc];
                mma_tf32(oacc[nt], a0, a1, a2, a3, b0, b1);
            }
        }
    }

    // epilogue: normalize, write Y[B,T,H,D]
    #pragma unroll
    for (int hh = 0; hh < 2; hh++) {
        float inv = 1.0f / l_[hh];
        int qg = qb * 64 + r0 + 8 * hh;
        size_t base = ((size_t)(b * TT + qg) * NH + h) * HD;
        #pragma unroll
        for (int nt = 0; nt < 8; nt++) {
            int d = nt * 8 + 2 * tig;
            float2 o2 = { oacc[nt][2 * hh] * inv, oacc[nt][2 * hh + 1] * inv };
            *(float2*)&Y[base + d] = o2;
        }
    }
}

// ---------------------------------------------------------------------------
extern "C" void kernel_launch(void* const* d_in, const int* in_sizes, int n_in,
                              void* d_out, int out_size)
{
    const float* x     = (const float*)d_in[0];   // [B,T,C]
    const float* Wqkv  = (const float*)d_in[1];   // [C, 3C]
    const float* Wproj = (const float*)d_in[2];   // [C, C]
    float* out = (float*)d_out;                   // [B,T,C]

    float *qkv, *q, *k, *v, *y;
    cudaGetSymbolAddress((void**)&qkv, g_qkv);
    cudaGetSymbolAddress((void**)&q,   g_q);
    cudaGetSymbolAddress((void**)&k,   g_k);
    cudaGetSymbolAddress((void**)&v,   g_v);
    cudaGetSymbolAddress((void**)&y,   g_y);

    // 1) qkv = x @ Wqkv   (8192 x 3072 x 1024)
    gemm_tf32<<<dim3(3 * DIMC / 128, BT / 128), 256>>>(x, Wqkv, qkv, BT, 3 * DIMC, DIMC);

    // 2) split + RoPE (+ q scaling)
    rope_split<<<(BT * DIMC + 255) / 256, 256>>>(qkv, q, k, v);

    // 3) causal flash attention (tensor cores, warp-owns-rows layout)
    const int smem_bytes = 64 * (KST + VST + PST) * (int)sizeof(uint32_t);  // 54272
    cudaFuncSetAttribute(attn_tc, cudaFuncAttributeMaxDynamicSharedMemorySize, smem_bytes);
    attn_tc<<<dim3(TT / 64, BB * NH), 128, smem_bytes>>>(q, k, v, y);

    // 4) out = y @ Wproj  (8192 x 1024 x 1024)
    gemm_tf32<<<dim3(DIMC / 128, BT / 128), 256>>>(y, Wproj, out, BT, DIMC, DIMC);
}

// round 13
// speedup vs baseline: 1.2659x; 1.0852x over previous
#include <cuda_runtime.h>
#include <cstdint>

#define DIMC 1024
#define NH 16
#define HD 64
#define BB 4
#define TT 2048
#define BT (BB*TT)   // 8192

// Scratch (device globals: allocation-free contract)
__device__ float g_qkv[BT * 3 * DIMC];   // 96 MB
__device__ float g_q[BT * DIMC];         // [B,H,T,D]
__device__ float g_k[BT * DIMC];
__device__ float g_v[BT * DIMC];
__device__ float g_y[BT * DIMC];         // attention out, [B,T,H,D] = [BT, C]

// ---------------------------------------------------------------------------
// TF32 helpers
// ---------------------------------------------------------------------------
__device__ __forceinline__ uint32_t f2tf32(float f) {
    uint32_t u;
    asm("cvt.rna.tf32.f32 %0, %1;" : "=r"(u) : "f"(f));
    return u;
}

__device__ __forceinline__ void mma_tf32(float c[4],
    uint32_t a0, uint32_t a1, uint32_t a2, uint32_t a3,
    uint32_t b0, uint32_t b1)
{
    asm volatile(
        "mma.sync.aligned.m16n8k8.row.col.f32.tf32.tf32.f32 "
        "{%0,%1,%2,%3}, {%4,%5,%6,%7}, {%8,%9}, {%0,%1,%2,%3};"
        : "+f"(c[0]), "+f"(c[1]), "+f"(c[2]), "+f"(c[3])
        : "r"(a0), "r"(a1), "r"(a2), "r"(a3), "r"(b0), "r"(b1));
}

// ---------------------------------------------------------------------------
// TF32 GEMM: C[M,N] = A[M,K] @ B[K,N], row-major fp32 in/out.
// Block 128x128, BK=16, 128 threads (4 warps, 2m x 2n), warp tile 64x64.
// Double-buffered smem + register prefetch: one __syncthreads per K-step.
// 32 independent MMA accumulators per warp per kc -> deep tensor-pipe ILP.
// ---------------------------------------------------------------------------
#define AST 20
#define BST 136
__global__ __launch_bounds__(128, 2) void gemm_tf32(
    const float* __restrict__ A, const float* __restrict__ Bm,
    float* __restrict__ C, int M, int N, int K)
{
    __shared__ uint32_t As[2][128 * AST];   // [m][k]
    __shared__ uint32_t Bs[2][16 * BST];    // [k][n]

    const int tid  = threadIdx.x;
    const int lane = tid & 31;
    const int warp = tid >> 5;           // 0..3
    const int wm = warp & 1;             // m half
    const int wn = warp >> 1;            // n half
    const int m0 = blockIdx.y << 7;
    const int n0 = blockIdx.x << 7;
    const int m0w = wm * 64;
    const int n0w = wn * 64;

    const int row = lane >> 2;
    const int tig = lane & 3;

    // staging indices: 4 float4 per thread for each of A (128x16) and B (16x128)
    int raA[4], caA[4], rbB[4], cbB[4];
    #pragma unroll
    for (int i = 0; i < 4; i++) {
        int idx = tid + i * 128;
        raA[i] = idx >> 2;  caA[i] = (idx & 3) << 2;
        rbB[i] = idx >> 5;  cbB[i] = (idx & 31) << 2;
    }

    float acc[4][8][4];                  // [mt][nt][reg]
    #pragma unroll
    for (int i = 0; i < 4; i++)
        #pragma unroll
        for (int j = 0; j < 8; j++)
            #pragma unroll
            for (int r = 0; r < 4; r++) acc[i][j][r] = 0.0f;

    const int KT = K >> 4;

    // prologue: load tile 0 into buffer 0
    float4 av[4], bv[4];
    #pragma unroll
    for (int i = 0; i < 4; i++) {
        av[i] = *(const float4*)&A[(size_t)(m0 + raA[i]) * K + caA[i]];
        bv[i] = *(const float4*)&Bm[(size_t)rbB[i] * N + n0 + cbB[i]];
    }
    #pragma unroll
    for (int i = 0; i < 4; i++) {
        uint4 u;
        u.x = f2tf32(av[i].x); u.y = f2tf32(av[i].y);
        u.z = f2tf32(av[i].z); u.w = f2tf32(av[i].w);
        *(uint4*)&As[0][raA[i] * AST + caA[i]] = u;
        u.x = f2tf32(bv[i].x); u.y = f2tf32(bv[i].y);
        u.z = f2tf32(bv[i].z); u.w = f2tf32(bv[i].w);
        *(uint4*)&Bs[0][rbB[i] * BST + cbB[i]] = u;
    }
    __syncthreads();

    for (int ki = 0; ki < KT; ki++) {
        const int cur = ki & 1;
        const int nxt = cur ^ 1;
        const bool more = (ki + 1) < KT;

        // prefetch next tile into registers (latency overlaps the MMAs below)
        if (more) {
            int k0 = (ki + 1) << 4;
            #pragma unroll
            for (int i = 0; i < 4; i++) {
                av[i] = *(const float4*)&A[(size_t)(m0 + raA[i]) * K + k0 + caA[i]];
                bv[i] = *(const float4*)&Bm[(size_t)(k0 + rbB[i]) * N + n0 + cbB[i]];
            }
        }

        const uint32_t* Ac = &As[cur][0];
        const uint32_t* Bc = &Bs[cur][0];
        #pragma unroll
        for (int kc = 0; kc < 16; kc += 8) {
            uint32_t af[4][4], bf[8][2];
            #pragma unroll
            for (int mt = 0; mt < 4; mt++) {
                int mr = m0w + mt * 16 + row;
                af[mt][0] = Ac[mr * AST + kc + tig];
                af[mt][1] = Ac[(mr + 8) * AST + kc + tig];
                af[mt][2] = Ac[mr * AST + kc + tig + 4];
                af[mt][3] = Ac[(mr + 8) * AST + kc + tig + 4];
            }
            #pragma unroll
            for (int nt = 0; nt < 8; nt++) {
                int nc = n0w + nt * 8 + row;
                bf[nt][0] = Bc[(kc + tig) * BST + nc];
                bf[nt][1] = Bc[(kc + tig + 4) * BST + nc];
            }
            #pragma unroll
            for (int mt = 0; mt < 4; mt++)
                #pragma unroll
                for (int nt = 0; nt < 8; nt++)
                    mma_tf32(acc[mt][nt], af[mt][0], af[mt][1], af[mt][2], af[mt][3],
                             bf[nt][0], bf[nt][1]);
        }

        // store prefetched tile into the other buffer
        if (more) {
            #pragma unroll
            for (int i = 0; i < 4; i++) {
                uint4 u;
                u.x = f2tf32(av[i].x); u.y = f2tf32(av[i].y);
                u.z = f2tf32(av[i].z); u.w = f2tf32(av[i].w);
                *(uint4*)&As[nxt][raA[i] * AST + caA[i]] = u;
                u.x = f2tf32(bv[i].x); u.y = f2tf32(bv[i].y);
                u.z = f2tf32(bv[i].z); u.w = f2tf32(bv[i].w);
                *(uint4*)&Bs[nxt][rbB[i] * BST + cbB[i]] = u;
            }
        }
        __syncthreads();
    }

    #pragma unroll
    for (int mt = 0; mt < 4; mt++) {
        int mr = m0 + m0w + mt * 16 + row;
        #pragma unroll
        for (int nt = 0; nt < 8; nt++) {
            int nc = n0 + n0w + nt * 8 + 2 * tig;
            float2 lo = { acc[mt][nt][0], acc[mt][nt][1] };
            float2 hi = { acc[mt][nt][2], acc[mt][nt][3] };
            *(float2*)&C[(size_t)mr * N + nc] = lo;
            *(float2*)&C[(size_t)(mr + 8) * N + nc] = hi;
        }
    }
}

// ---------------------------------------------------------------------------
// RoPE + split + reshape (unchanged)
// ---------------------------------------------------------------------------
__global__ __launch_bounds__(256) void rope_split(
    const float* __restrict__ qkv,
    float* __restrict__ Q, float* __restrict__ K, float* __restrict__ V)
{
    int gid = blockIdx.x * 256 + threadIdx.x;
    if (gid >= BT * DIMC) return;

    int d  = gid & 63;
    int h  = (gid >> 6) & 15;
    int bt = gid >> 10;
    int t  = bt & (TT - 1);
    int b  = bt >> 11;

    const float* row = qkv + (size_t)bt * (3 * DIMC);

    int j = d & 31;
    float freq = __expf(-(float)j * 0.28782313662425575f);
    float ang = (float)t * freq;
    float s, c;
    sincosf(ang, &s, &c);

    int pair = (d < 32) ? d + 32 : d - 32;
    float sign = (d < 32) ? -1.0f : 1.0f;

    float qv = row[h * 64 + d];
    float qp = row[h * 64 + pair];
    float kv = row[DIMC + h * 64 + d];
    float kp = row[DIMC + h * 64 + pair];
    float vv = row[2 * DIMC + h * 64 + d];

    size_t o = ((size_t)(b * NH + h) * TT + t) * HD + d;
    Q[o] = (qv * c + sign * qp * s) * 0.125f;
    K[o] =  kv * c + sign * kp * s;
    V[o] =  vv;
}

// ---------------------------------------------------------------------------
// Tensor-core flash attention (causal). 64x64 tiles, 128 threads (4 warps).
// Each warp owns 16 full query rows (m16 x n64) -> softmax is warp-local.
// Single-TF32 QK (Q frags in registers), TF32 PV. Conflict-free smem strides.
// (unchanged from the 909us version)
// ---------------------------------------------------------------------------
#define KST 68
#define VST 72
#define PST 72
__global__ __launch_bounds__(128) void attn_tc(
    const float* __restrict__ Q, const float* __restrict__ K,
    const float* __restrict__ V, float* __restrict__ Y)
{
    extern __shared__ uint32_t smw[];
    uint32_t* Ks = smw;                // [kseq][d]  64 x KST
    uint32_t* Vs = Ks + 64 * KST;      // [kseq][d]  64 x VST
    uint32_t* Ps = Vs + 64 * VST;      // [q][kseq]  64 x PST

    const int tid  = threadIdx.x;
    const int lane = tid & 31;
    const int warp = tid >> 5;         // 0..3
    const int row  = lane >> 2;        // 0..7
    const int tig  = lane & 3;         // 0..3
    const int qb = blockIdx.x;
    const int bh = blockIdx.y;
    const int b  = bh >> 4;
    const int h  = bh & 15;
    const int r0 = warp * 16 + row;    // owned rows r0, r0+8

    const float* Qg = Q + ((size_t)bh * TT + qb * 64) * HD;
    const float* Kg = K + (size_t)bh * TT * HD;
    const float* Vg = V + (size_t)bh * TT * HD;

    uint32_t qh[8][4];
    #pragma unroll
    for (int s = 0; s < 8; s++) {
        qh[s][0] = f2tf32(Qg[r0 * 64 + 8 * s + tig]);
        qh[s][1] = f2tf32(Qg[(r0 + 8) * 64 + 8 * s + tig]);
        qh[s][2] = f2tf32(Qg[r0 * 64 + 8 * s + tig + 4]);
        qh[s][3] = f2tf32(Qg[(r0 + 8) * 64 + 8 * s + tig + 4]);
    }

    float m_[2] = { -1e30f, -1e30f };
    float l_[2] = { 0.0f, 0.0f };
    float oacc[8][4];
    #pragma unroll
    for (int nt = 0; nt < 8; nt++)
        #pragma unroll
        for (int r = 0; r < 4; r++) oacc[nt][r] = 0.0f;

    for (int kb = 0; kb <= qb; kb++) {
        __syncthreads();   // all warps done reading Ks/Vs from previous iter
        #pragma unroll
        for (int it = 0; it < 8; it++) {
            int idx = tid + it * 128;
            int k  = idx >> 4;
            int d0 = (idx & 15) << 2;
            float4 kv = *(const float4*)&Kg[(size_t)(kb * 64 + k) * 64 + d0];
            float4 vv = *(const float4*)&Vg[(size_t)(kb * 64 + k) * 64 + d0];
            uint4 ku = { f2tf32(kv.x), f2tf32(kv.y), f2tf32(kv.z), f2tf32(kv.w) };
            uint4 vu = { f2tf32(vv.x), f2tf32(vv.y), f2tf32(vv.z), f2tf32(vv.w) };
            *(uint4*)&Ks[k * KST + d0] = ku;
            *(uint4*)&Vs[k * VST + d0] = vu;
        }
        __syncthreads();

        float sacc[8][4];
        #pragma unroll
        for (int nt = 0; nt < 8; nt++)
            #pragma unroll
            for (int r = 0; r < 4; r++) sacc[nt][r] = 0.0f;

        #pragma unroll
        for (int s = 0; s < 8; s++) {
            int kc = 8 * s;
            #pragma unroll
            for (int nt = 0; nt < 8; nt++) {
                int nc = nt * 8 + row;
                uint32_t b0 = Ks[nc * KST + kc + tig];
                uint32_t b1 = Ks[nc * KST + kc + tig + 4];
                mma_tf32(sacc[nt], qh[s][0], qh[s][1], qh[s][2], qh[s][3], b0, b1);
            }
        }

        if (kb == qb) {
            #pragma unroll
            for (int nt = 0; nt < 8; nt++)
                #pragma unroll
                for (int r = 0; r < 4; r++) {
                    int ql = r0 + 8 * (r >> 1);
                    int kl = nt * 8 + 2 * tig + (r & 1);
                    if (kl > ql) sacc[nt][r] = -1e30f;
                }
        }

        #pragma unroll
        for (int hh = 0; hh < 2; hh++) {
            float mx = -1e30f;
            #pragma unroll
            for (int nt = 0; nt < 8; nt++)
                mx = fmaxf(mx, fmaxf(sacc[nt][2 * hh], sacc[nt][2 * hh + 1]));
            mx = fmaxf(mx, __shfl_xor_sync(0xffffffffu, mx, 1));
            mx = fmaxf(mx, __shfl_xor_sync(0xffffffffu, mx, 2));
            float mnew = fmaxf(m_[hh], mx);
            float alpha = __expf(m_[hh] - mnew);
            m_[hh] = mnew;
            float rs = 0.0f;
            int qrow = r0 + 8 * hh;
            #pragma unroll
            for (int nt = 0; nt < 8; nt++) {
                float p0 = __expf(sacc[nt][2 * hh] - mnew);
                float p1 = __expf(sacc[nt][2 * hh + 1] - mnew);
                rs += p0 + p1;
                uint2 pu = { f2tf32(p0), f2tf32(p1) };
                *(uint2*)&Ps[qrow * PST + nt * 8 + 2 * tig] = pu;
                oacc[nt][2 * hh]     *= alpha;
                oacc[nt][2 * hh + 1] *= alpha;
            }
            rs += __shfl_xor_sync(0xffffffffu, rs, 1);
            rs += __shfl_xor_sync(0xffffffffu, rs, 2);
            l_[hh] = l_[hh] * alpha + rs;
        }
        __syncwarp();

        #pragma unroll
        for (int s = 0; s < 8; s++) {
            int kc = 8 * s;
            uint32_t a0 = Ps[r0 * PST + kc + tig];
            uint32_t a1 = Ps[(r0 + 8) * PST + kc + tig];
            uint32_t a2 = Ps[r0 * PST + kc + tig + 4];
            uint32_t a3 = Ps[(r0 + 8) * PST + kc + tig + 4];
            #pragma unroll
            for (int nt = 0; nt < 8; nt++) {
                int nc = nt * 8 + row;
                uint32_t b0 = Vs[(kc + tig) * VST + nc];
                uint32_t b1 = Vs[(kc + tig + 4) * VST + nc];
                mma_tf32(oacc[nt], a0, a1, a2, a3, b0, b1);
            }
        }
    }

    #pragma unroll
    for (int hh = 0; hh < 2; hh++) {
        float inv = 1.0f / l_[hh];
        int qg = qb * 64 + r0 + 8 * hh;
        size_t base = ((size_t)(b * TT + qg) * NH + h) * HD;
        #pragma unroll
        for (int nt = 0; nt < 8; nt++) {
            int d = nt * 8 + 2 * tig;
            float2 o2 = { oacc[nt][2 * hh] * inv, oacc[nt][2 * hh + 1] * inv };
            *(float2*)&Y[base + d] = o2;
        }
    }
}

// ---------------------------------------------------------------------------
extern "C" void kernel_launch(void* const* d_in, const int* in_sizes, int n_in,
                              void* d_out, int out_size)
{
    const float* x     = (const float*)d_in[0];   // [B,T,C]
    const float* Wqkv  = (const float*)d_in[1];   // [C, 3C]
    const float* Wproj = (const float*)d_in[2];   // [C, C]
    float* out = (float*)d_out;                   // [B,T,C]

    float *qkv, *q, *k, *v, *y;
    cudaGetSymbolAddress((void**)&qkv, g_qkv);
    cudaGetSymbolAddress((void**)&q,   g_q);
    cudaGetSymbolAddress((void**)&k,   g_k);
    cudaGetSymbolAddress((void**)&v,   g_v);
    cudaGetSymbolAddress((void**)&y,   g_y);

    // 1) qkv = x @ Wqkv   (8192 x 3072 x 1024)
    gemm_tf32<<<dim3(3 * DIMC / 128, BT / 128), 128>>>(x, Wqkv, qkv, BT, 3 * DIMC, DIMC);

    // 2) split + RoPE (+ q scaling)
    rope_split<<<(BT * DIMC + 255) / 256, 256>>>(qkv, q, k, v);

    // 3) causal flash attention (tensor cores, warp-owns-rows layout)
    const int smem_bytes = 64 * (KST + VST + PST) * (int)sizeof(uint32_t);  // 54272
    cudaFuncSetAttribute(attn_tc, cudaFuncAttributeMaxDynamicSharedMemorySize, smem_bytes);
    attn_tc<<<dim3(TT / 64, BB * NH), 128, smem_bytes>>>(q, k, v, y);

    // 4) out = y @ Wproj  (8192 x 1024 x 1024)
    gemm_tf32<<<dim3(DIMC / 128, BT / 128), 128>>>(y, Wproj, out, BT, DIMC, DIMC);
}

// round 14
// speedup vs baseline: 1.3157x; 1.0393x over previous
#include <cuda_runtime.h>
#include <cstdint>

#define DIMC 1024
#define NH 16
#define HD 64
#define BB 4
#define TT 2048
#define BT (BB*TT)   // 8192

// Scratch (device globals: allocation-free contract)
__device__ float g_q[BT * DIMC];         // [B,H,T,D]
__device__ float g_k[BT * DIMC];
__device__ float g_v[BT * DIMC];
__device__ float g_y[BT * DIMC];         // attention out, [B,T,H,D] = [BT, C]
__device__ float g_rope[TT * 32 * 2];    // interleaved (cos, sin) per (t, j)

// ---------------------------------------------------------------------------
// TF32 helpers
// ---------------------------------------------------------------------------
__device__ __forceinline__ uint32_t f2tf32(float f) {
    uint32_t u;
    asm("cvt.rna.tf32.f32 %0, %1;" : "=r"(u) : "f"(f));
    return u;
}

__device__ __forceinline__ void mma_tf32(float c[4],
    uint32_t a0, uint32_t a1, uint32_t a2, uint32_t a3,
    uint32_t b0, uint32_t b1)
{
    asm volatile(
        "mma.sync.aligned.m16n8k8.row.col.f32.tf32.tf32.f32 "
        "{%0,%1,%2,%3}, {%4,%5,%6,%7}, {%8,%9}, {%0,%1,%2,%3};"
        : "+f"(c[0]), "+f"(c[1]), "+f"(c[2]), "+f"(c[3])
        : "r"(a0), "r"(a1), "r"(a2), "r"(a3), "r"(b0), "r"(b1));
}

// ---------------------------------------------------------------------------
// RoPE table init: g_rope[(t*32+j)*2] = cos(t*freq_j), +1 = sin(t*freq_j).
// Same __expf / sincosf expressions as the old rope_split -> identical bits.
// ---------------------------------------------------------------------------
__global__ void rope_init(float* R) {
    int i = blockIdx.x * 256 + threadIdx.x;      // TT*32 = 65536
    if (i >= TT * 32) return;
    int t = i >> 5, j = i & 31;
    float freq = __expf(-(float)j * 0.28782313662425575f);
    float s, c;
    sincosf((float)t * freq, &s, &c);
    R[i * 2]     = c;
    R[i * 2 + 1] = s;
}

// ---------------------------------------------------------------------------
// TF32 GEMM: C[M,N] = A[M,K] @ B[K,N], row-major fp32 in/out.
// Block 128x128, BK=16, 128 threads (4 warps, 2m x 2n), warp tile 64x64.
// Double-buffered smem + register prefetch: one __syncthreads per K-step.
// MODE 0: plain store to C.
// MODE 1: fused RoPE+split epilogue for the qkv GEMM (N=3072). Each warp
//   tile spans exactly one 64-wide head; the RoPE pair (d <-> d^32) is
//   fragment nt <-> nt^4 in the SAME thread, so RoPE is applied in registers
//   and rows are scattered to Q/K/V in [B,H,T,D] (Q pre-scaled by 1/8).
// ---------------------------------------------------------------------------
#define AST 20
#define BST 136
template<int MODE>
__global__ __launch_bounds__(128, 2) void gemm_tf32(
    const float* __restrict__ A, const float* __restrict__ Bm,
    float* __restrict__ C, int M, int N, int K,
    float* __restrict__ Qd, float* __restrict__ Kd, float* __restrict__ Vd,
    const float* __restrict__ Rope)
{
    __shared__ uint32_t As[2][128 * AST];   // [m][k]
    __shared__ uint32_t Bs[2][16 * BST];    // [k][n]

    const int tid  = threadIdx.x;
    const int lane = tid & 31;
    const int warp = tid >> 5;           // 0..3
    const int wm = warp & 1;             // m half
    const int wn = warp >> 1;            // n half
    const int m0 = blockIdx.y << 7;
    const int n0 = blockIdx.x << 7;
    const int m0w = wm * 64;
    const int n0w = wn * 64;

    const int row = lane >> 2;
    const int tig = lane & 3;

    int raA[4], caA[4], rbB[4], cbB[4];
    #pragma unroll
    for (int i = 0; i < 4; i++) {
        int idx = tid + i * 128;
        raA[i] = idx >> 2;  caA[i] = (idx & 3) << 2;
        rbB[i] = idx >> 5;  cbB[i] = (idx & 31) << 2;
    }

    float acc[4][8][4];                  // [mt][nt][reg]
    #pragma unroll
    for (int i = 0; i < 4; i++)
        #pragma unroll
        for (int j = 0; j < 8; j++)
            #pragma unroll
            for (int r = 0; r < 4; r++) acc[i][j][r] = 0.0f;

    const int KT = K >> 4;

    float4 av[4], bv[4];
    #pragma unroll
    for (int i = 0; i < 4; i++) {
        av[i] = *(const float4*)&A[(size_t)(m0 + raA[i]) * K + caA[i]];
        bv[i] = *(const float4*)&Bm[(size_t)rbB[i] * N + n0 + cbB[i]];
    }
    #pragma unroll
    for (int i = 0; i < 4; i++) {
        uint4 u;
        u.x = f2tf32(av[i].x); u.y = f2tf32(av[i].y);
        u.z = f2tf32(av[i].z); u.w = f2tf32(av[i].w);
        *(uint4*)&As[0][raA[i] * AST + caA[i]] = u;
        u.x = f2tf32(bv[i].x); u.y = f2tf32(bv[i].y);
        u.z = f2tf32(bv[i].z); u.w = f2tf32(bv[i].w);
        *(uint4*)&Bs[0][rbB[i] * BST + cbB[i]] = u;
    }
    __syncthreads();

    for (int ki = 0; ki < KT; ki++) {
        const int cur = ki & 1;
        const int nxt = cur ^ 1;
        const bool more = (ki + 1) < KT;

        if (more) {
            int k0 = (ki + 1) << 4;
            #pragma unroll
            for (int i = 0; i < 4; i++) {
                av[i] = *(const float4*)&A[(size_t)(m0 + raA[i]) * K + k0 + caA[i]];
                bv[i] = *(const float4*)&Bm[(size_t)(k0 + rbB[i]) * N + n0 + cbB[i]];
            }
        }

        const uint32_t* Ac = &As[cur][0];
        const uint32_t* Bc = &Bs[cur][0];
        #pragma unroll
        for (int kc = 0; kc < 16; kc += 8) {
            uint32_t af[4][4], bf[8][2];
            #pragma unroll
            for (int mt = 0; mt < 4; mt++) {
                int mr = m0w + mt * 16 + row;
                af[mt][0] = Ac[mr * AST + kc + tig];
                af[mt][1] = Ac[(mr + 8) * AST + kc + tig];
                af[mt][2] = Ac[mr * AST + kc + tig + 4];
                af[mt][3] = Ac[(mr + 8) * AST + kc + tig + 4];
            }
            #pragma unroll
            for (int nt = 0; nt < 8; nt++) {
                int nc = n0w + nt * 8 + row;
                bf[nt][0] = Bc[(kc + tig) * BST + nc];
                bf[nt][1] = Bc[(kc + tig + 4) * BST + nc];
            }
            #pragma unroll
            for (int mt = 0; mt < 4; mt++)
                #pragma unroll
                for (int nt = 0; nt < 8; nt++)
                    mma_tf32(acc[mt][nt], af[mt][0], af[mt][1], af[mt][2], af[mt][3],
                             bf[nt][0], bf[nt][1]);
        }

        if (more) {
            #pragma unroll
            for (int i = 0; i < 4; i++) {
                uint4 u;
                u.x = f2tf32(av[i].x); u.y = f2tf32(av[i].y);
                u.z = f2tf32(av[i].z); u.w = f2tf32(av[i].w);
                *(uint4*)&As[nxt][raA[i] * AST + caA[i]] = u;
                u.x = f2tf32(bv[i].x); u.y = f2tf32(bv[i].y);
                u.z = f2tf32(bv[i].z); u.w = f2tf32(bv[i].w);
                *(uint4*)&Bs[nxt][rbB[i] * BST + cbB[i]] = u;
            }
        }
        __syncthreads();
    }

    if (MODE == 0) {
        #pragma unroll
        for (int mt = 0; mt < 4; mt++) {
            int mr = m0 + m0w + mt * 16 + row;
            #pragma unroll
            for (int nt = 0; nt < 8; nt++) {
                int nc = n0 + n0w + nt * 8 + 2 * tig;
                float2 lo = { acc[mt][nt][0], acc[mt][nt][1] };
                float2 hi = { acc[mt][nt][2], acc[mt][nt][3] };
                *(float2*)&C[(size_t)mr * N + nc] = lo;
                *(float2*)&C[(size_t)(mr + 8) * N + nc] = hi;
            }
        }
    } else {
        // fused RoPE + split epilogue (qkv GEMM, N = 3072)
        const int seg  = n0 >> 10;                       // 0=q, 1=k, 2=v
        const int head = ((n0 & 1023) + n0w) >> 6;       // warp tile = 1 head
        float* dst = (seg == 0) ? Qd : (seg == 1) ? Kd : Vd;
        const float scale = (seg == 0) ? 0.125f : 1.0f;

        #pragma unroll
        for (int mt = 0; mt < 4; mt++) {
            #pragma unroll
            for (int half = 0; half < 2; half++) {
                const int bt = m0 + m0w + mt * 16 + row + half * 8;
                const int t = bt & (TT - 1);
                const int b = bt >> 11;
                const size_t base = ((size_t)(b * NH + head) * TT + t) * HD;
                if (seg == 2) {
                    #pragma unroll
                    for (int nt = 0; nt < 8; nt++) {
                        float2 o = { acc[mt][nt][half * 2], acc[mt][nt][half * 2 + 1] };
                        *(float2*)&dst[base + nt * 8 + 2 * tig] = o;
                    }
                } else {
                    float4 tb[4];   // {cos(j), sin(j), cos(j+1), sin(j+1)} for j=8q+2tig
                    #pragma unroll
                    for (int q = 0; q < 4; q++)
                        tb[q] = *(const float4*)&Rope[(t * 32 + q * 8 + 2 * tig) * 2];
                    #pragma unroll
                    for (int nt = 0; nt < 8; nt++) {
                        const int q = nt & 3;
                        const float sg = (nt < 4) ? -1.0f : 1.0f;
                        float v0 = acc[mt][nt][half * 2];
                        float v1 = acc[mt][nt][half * 2 + 1];
                        float p0 = acc[mt][nt ^ 4][half * 2];
                        float p1 = acc[mt][nt ^ 4][half * 2 + 1];
                        float2 o = { (v0 * tb[q].x + sg * p0 * tb[q].y) * scale,
                                     (v1 * tb[q].z + sg * p1 * tb[q].w) * scale };
                        *(float2*)&dst[base + nt * 8 + 2 * tig] = o;
                    }
                }
            }
        }
    }
}

// ---------------------------------------------------------------------------
// Tensor-core flash attention (causal). 64x64 tiles, 128 threads (4 warps).
// (unchanged from the 838us version)
// ---------------------------------------------------------------------------
#define KST 68
#define VST 72
#define PST 72
__global__ __launch_bounds__(128) void attn_tc(
    const float* __restrict__ Q, const float* __restrict__ K,
    const float* __restrict__ V, float* __restrict__ Y)
{
    extern __shared__ uint32_t smw[];
    uint32_t* Ks = smw;                // [kseq][d]  64 x KST
    uint32_t* Vs = Ks + 64 * KST;      // [kseq][d]  64 x VST
    uint32_t* Ps = Vs + 64 * VST;      // [q][kseq]  64 x PST

    const int tid  = threadIdx.x;
    const int lane = tid & 31;
    const int warp = tid >> 5;         // 0..3
    const int row  = lane >> 2;        // 0..7
    const int tig  = lane & 3;         // 0..3
    const int qb = blockIdx.x;
    const int bh = blockIdx.y;
    const int b  = bh >> 4;
    const int h  = bh & 15;
    const int r0 = warp * 16 + row;    // owned rows r0, r0+8

    const float* Qg = Q + ((size_t)bh * TT + qb * 64) * HD;
    const float* Kg = K + (size_t)bh * TT * HD;
    const float* Vg = V + (size_t)bh * TT * HD;

    uint32_t qh[8][4];
    #pragma unroll
    for (int s = 0; s < 8; s++) {
        qh[s][0] = f2tf32(Qg[r0 * 64 + 8 * s + tig]);
        qh[s][1] = f2tf32(Qg[(r0 + 8) * 64 + 8 * s + tig]);
        qh[s][2] = f2tf32(Qg[r0 * 64 + 8 * s + tig + 4]);
        qh[s][3] = f2tf32(Qg[(r0 + 8) * 64 + 8 * s + tig + 4]);
    }

    float m_[2] = { -1e30f, -1e30f };
    float l_[2] = { 0.0f, 0.0f };
    float oacc[8][4];
    #pragma unroll
    for (int nt = 0; nt < 8; nt++)
        #pragma unroll
        for (int r = 0; r < 4; r++) oacc[nt][r] = 0.0f;

    for (int kb = 0; kb <= qb; kb++) {
        __syncthreads();
        #pragma unroll
        for (int it = 0; it < 8; it++) {
            int idx = tid + it * 128;
            int k  = idx >> 4;
            int d0 = (idx & 15) << 2;
            float4 kv = *(const float4*)&Kg[(size_t)(kb * 64 + k) * 64 + d0];
            float4 vv = *(const float4*)&Vg[(size_t)(kb * 64 + k) * 64 + d0];
            uint4 ku = { f2tf32(kv.x), f2tf32(kv.y), f2tf32(kv.z), f2tf32(kv.w) };
            uint4 vu = { f2tf32(vv.x), f2tf32(vv.y), f2tf32(vv.z), f2tf32(vv.w) };
            *(uint4*)&Ks[k * KST + d0] = ku;
            *(uint4*)&Vs[k * VST + d0] = vu;
        }
        __syncthreads();

        float sacc[8][4];
        #pragma unroll
        for (int nt = 0; nt < 8; nt++)
            #pragma unroll
            for (int r = 0; r < 4; r++) sacc[nt][r] = 0.0f;

        #pragma unroll
        for (int s = 0; s < 8; s++) {
            int kc = 8 * s;
            #pragma unroll
            for (int nt = 0; nt < 8; nt++) {
                int nc = nt * 8 + row;
                uint32_t b0 = Ks[nc * KST + kc + tig];
                uint32_t b1 = Ks[nc * KST + kc + tig + 4];
                mma_tf32(sacc[nt], qh[s][0], qh[s][1], qh[s][2], qh[s][3], b0, b1);
            }
        }

        if (kb == qb) {
            #pragma unroll
            for (int nt = 0; nt < 8; nt++)
                #pragma unroll
                for (int r = 0; r < 4; r++) {
                    int ql = r0 + 8 * (r >> 1);
                    int kl = nt * 8 + 2 * tig + (r & 1);
                    if (kl > ql) sacc[nt][r] = -1e30f;
                }
        }

        #pragma unroll
        for (int hh = 0; hh < 2; hh++) {
            float mx = -1e30f;
            #pragma unroll
            for (int nt = 0; nt < 8; nt++)
                mx = fmaxf(mx, fmaxf(sacc[nt][2 * hh], sacc[nt][2 * hh + 1]));
            mx = fmaxf(mx, __shfl_xor_sync(0xffffffffu, mx, 1));
            mx = fmaxf(mx, __shfl_xor_sync(0xffffffffu, mx, 2));
            float mnew = fmaxf(m_[hh], mx);
            float alpha = __expf(m_[hh] - mnew);
            m_[hh] = mnew;
            float rs = 0.0f;
            int qrow = r0 + 8 * hh;
            #pragma unroll
            for (int nt = 0; nt < 8; nt++) {
                float p0 = __expf(sacc[nt][2 * hh] - mnew);
                float p1 = __expf(sacc[nt][2 * hh + 1] - mnew);
                rs += p0 + p1;
                uint2 pu = { f2tf32(p0), f2tf32(p1) };
                *(uint2*)&Ps[qrow * PST + nt * 8 + 2 * tig] = pu;
                oacc[nt][2 * hh]     *= alpha;
                oacc[nt][2 * hh + 1] *= alpha;
            }
            rs += __shfl_xor_sync(0xffffffffu, rs, 1);
            rs += __shfl_xor_sync(0xffffffffu, rs, 2);
            l_[hh] = l_[hh] * alpha + rs;
        }
        __syncwarp();

        #pragma unroll
        for (int s = 0; s < 8; s++) {
            int kc = 8 * s;
            uint32_t a0 = Ps[r0 * PST + kc + tig];
            uint32_t a1 = Ps[(r0 + 8) * PST + kc + tig];
            uint32_t a2 = Ps[r0 * PST + kc + tig + 4];
            uint32_t a3 = Ps[(r0 + 8) * PST + kc + tig + 4];
            #pragma unroll
            for (int nt = 0; nt < 8; nt++) {
                int nc = nt * 8 + row;
                uint32_t b0 = Vs[(kc + tig) * VST + nc];
                uint32_t b1 = Vs[(kc + tig + 4) * VST + nc];
                mma_tf32(oacc[nt], a0, a1, a2, a3, b0, b1);
            }
        }
    }

    #pragma unroll
    for (int hh = 0; hh < 2; hh++) {
        float inv = 1.0f / l_[hh];
        int qg = qb * 64 + r0 + 8 * hh;
        size_t base = ((size_t)(b * TT + qg) * NH + h) * HD;
        #pragma unroll
        for (int nt = 0; nt < 8; nt++) {
            int d = nt * 8 + 2 * tig;
            float2 o2 = { oacc[nt][2 * hh] * inv, oacc[nt][2 * hh + 1] * inv };
            *(float2*)&Y[base + d] = o2;
        }
    }
}

// ---------------------------------------------------------------------------
extern "C" void kernel_launch(void* const* d_in, const int* in_sizes, int n_in,
                              void* d_out, int out_size)
{
    const float* x     = (const float*)d_in[0];   // [B,T,C]
    const float* Wqkv  = (const float*)d_in[1];   // [C, 3C]
    const float* Wproj = (const float*)d_in[2];   // [C, C]
    float* out = (float*)d_out;                   // [B,T,C]

    float *q, *k, *v, *y, *rope;
    cudaGetSymbolAddress((void**)&q,    g_q);
    cudaGetSymbolAddress((void**)&k,    g_k);
    cudaGetSymbolAddress((void**)&v,    g_v);
    cudaGetSymbolAddress((void**)&y,    g_y);
    cudaGetSymbolAddress((void**)&rope, g_rope);

    // 0) RoPE cos/sin table
    rope_init<<<(TT * 32 + 255) / 256, 256>>>(rope);

    // 1) qkv = x @ Wqkv with fused RoPE + head-split epilogue
    gemm_tf32<1><<<dim3(3 * DIMC / 128, BT / 128), 128>>>(
        x, Wqkv, nullptr, BT, 3 * DIMC, DIMC, q, k, v, rope);

    // 2) causal flash attention (tensor cores, warp-owns-rows layout)
    const int smem_bytes = 64 * (KST + VST + PST) * (int)sizeof(uint32_t);  // 54272
    cudaFuncSetAttribute(attn_tc, cudaFuncAttributeMaxDynamicSharedMemorySize, smem_bytes);
    attn_tc<<<dim3(TT / 64, BB * NH), 128, smem_bytes>>>(q, k, v, y);

    // 3) out = y @ Wproj  (8192 x 1024 x 1024)
    gemm_tf32<0><<<dim3(DIMC / 128, BT / 128), 128>>>(
        y, Wproj, out, BT, DIMC, DIMC, nullptr, nullptr, nullptr, nullptr);
}